// round 9
// baseline (speedup 1.0000x reference)
#include <cuda_runtime.h>
#include <cstdint>
#include <math.h>

// Problem constants
#define BB 16
#define CC 32
#define TT 512
#define SS 128       // GAF_SIZE
#define NIMG (BB*CC) // 512
#define LATENT 128

// ---------------- scratch (no allocation allowed) ----------------
__device__ float g_gaf[(size_t)NIMG * 2 * SS * SS];      // NCHW (input to L1)
__device__ float g_h1 [(size_t)NIMG * 64 * 64 * 32];     // NHWC, tf32-rounded
__device__ float g_h2 [(size_t)NIMG * 32 * 32 * 64];     // NHWC, tf32-rounded
__device__ float g_h3 [(size_t)NIMG * 16 * 16 * 128];    // NHWC, tf32-rounded
__device__ float g_h4 [(size_t)NIMG * 8 * 8 * 256];      // NHWC, fp32
__device__ float g_pp  [NIMG * 256];
__device__ float g_pbar[BB * 256];
__device__ float g_wr1[2 * 9 * 32];                      // L1: [ci][t][cout]
__device__ float g_wr2[(32 * 9)  * 64];                  // [k][cout], tf32 bits
__device__ float g_wr3[(64 * 9)  * 128];
__device__ float g_wr4[(128 * 9) * 256];

// ---------------- helpers ----------------
__device__ __forceinline__ uint32_t f2tf32(float f) {
    uint32_t o;
    asm("cvt.rna.tf32.f32 %0, %1;" : "=r"(o) : "f"(f));
    return o;
}
__device__ __forceinline__ float f2tf32f(float f) {
    return __uint_as_float(f2tf32(f));
}
__device__ __forceinline__ void mma_tf32(float* d, const uint32_t* a, const uint32_t* b) {
    asm volatile(
        "mma.sync.aligned.m16n8k8.row.col.f32.tf32.tf32.f32 "
        "{%0,%1,%2,%3}, {%4,%5,%6,%7}, {%8,%9}, {%0,%1,%2,%3};"
        : "+f"(d[0]), "+f"(d[1]), "+f"(d[2]), "+f"(d[3])
        : "r"(a[0]), "r"(a[1]), "r"(a[2]), "r"(a[3]), "r"(b[0]), "r"(b[1]));
}
__device__ __forceinline__ uint32_t smem_u32(const void* p) {
    uint32_t a;
    asm("{ .reg .u64 t; cvta.to.shared.u64 t, %1; cvt.u32.u64 %0, t; }" : "=r"(a) : "l"(p));
    return a;
}
__device__ __forceinline__ void cpasync16(uint32_t dst, const void* src, int srcsize) {
    asm volatile("cp.async.cg.shared.global [%0], [%1], 16, %2;"
                 :: "r"(dst), "l"(src), "r"(srcsize) : "memory");
}
#define CP_COMMIT() asm volatile("cp.async.commit_group;" ::: "memory")
#define CP_WAIT1()  asm volatile("cp.async.wait_group 1;" ::: "memory")
#define CP_WAIT0()  asm volatile("cp.async.wait_group 0;" ::: "memory")

// ---------------- f32x2 helpers (L1 conv) ----------------
__device__ __forceinline__ unsigned long long pk2(float a, float b) {
    unsigned long long r;
    asm("mov.b64 %0, {%1, %2};" : "=l"(r) : "f"(a), "f"(b));
    return r;
}
__device__ __forceinline__ void upk2(unsigned long long v, float& a, float& b) {
    asm("mov.b64 {%0, %1}, %2;" : "=f"(a), "=f"(b) : "l"(v));
}
__device__ __forceinline__ void fma2(unsigned long long& d, unsigned long long a, unsigned long long b) {
    asm("fma.rn.f32x2 %0, %1, %2, %3;" : "=l"(d) : "l"(a), "l"(b), "l"(d));
}

// ---------------- merged weight repack ----------------
__device__ __forceinline__ void rp_tc(const float* __restrict__ W, uint32_t* __restrict__ Br,
                                      int CIN, int COUT, int idx)
{
    int co = idx % COUT;
    int k  = idx / COUT;
    int t  = k / CIN;
    int ci = k % CIN;
    Br[idx] = f2tf32(W[((size_t)co * CIN + ci) * 9 + t]);
}
__global__ void repack_all(const float* __restrict__ W1, const float* __restrict__ W2,
                           const float* __restrict__ W3, const float* __restrict__ W4)
{
    int idx = blockIdx.x * blockDim.x + threadIdx.x;
    if (idx < 576) {                       // L1: W[32][2][3][3] -> [ci][t][cout]
        int co = idx % 32;
        int t  = (idx / 32) % 9;
        int ci = idx / (32 * 9);
        g_wr1[idx] = W1[((size_t)co * 2 + ci) * 9 + t];
        return;
    }
    idx -= 576;
    if (idx < 288 * 64)  { rp_tc(W2, (uint32_t*)g_wr2, 32, 64, idx);  return; }
    idx -= 288 * 64;
    if (idx < 576 * 128) { rp_tc(W3, (uint32_t*)g_wr3, 64, 128, idx); return; }
    idx -= 576 * 128;
    if (idx < 1152 * 256) rp_tc(W4, (uint32_t*)g_wr4, 128, 256, idx);
}

// ---------------- GAF kernel (NCHW out), coalesced row stores ----------------
__global__ void gaf_kernel(const float* __restrict__ x_raw)
{
    const int img = blockIdx.x;
    const int tid = threadIdx.x;   // 0..127
    __shared__ float xs[SS];
    __shared__ float ssq[SS];
    __shared__ float smn[4], smx[4];

    const float4 v4 = *(const float4*)(x_raw + (size_t)img * TT + tid * 4);
    float v = 0.25f * (v4.x + v4.y + v4.z + v4.w);

    float mn = v, mx = v;
    #pragma unroll
    for (int o = 16; o > 0; o >>= 1) {
        mn = fminf(mn, __shfl_xor_sync(0xffffffffu, mn, o));
        mx = fmaxf(mx, __shfl_xor_sync(0xffffffffu, mx, o));
    }
    const int warp = tid >> 5, lane = tid & 31;
    if (lane == 0) { smn[warp] = mn; smx[warp] = mx; }
    __syncthreads();
    mn = fminf(fminf(smn[0], smn[1]), fminf(smn[2], smn[3]));
    mx = fmaxf(fmaxf(smx[0], smx[1]), fmaxf(smx[2], smx[3]));

    float xn = 2.0f * (v - mn) / (mx - mn + 1e-8f) - 1.0f;
    xn = fminf(1.0f, fmaxf(-1.0f, xn));
    float sq = sqrtf(fminf(1.0f, fmaxf(0.0f, 1.0f - xn * xn)));
    xs[tid] = xn;
    ssq[tid] = sq;
    __syncthreads();

    const int c0 = lane * 4;
    float xj[4], sj[4];
    #pragma unroll
    for (int c = 0; c < 4; c++) { xj[c] = xs[c0 + c]; sj[c] = ssq[c0 + c]; }
    float* __restrict__ g0 = g_gaf + (size_t)img * (2 * SS * SS);
    float* __restrict__ g1 = g0 + SS * SS;
    for (int rb = 0; rb < SS; rb += 4) {
        const int row = rb + warp;
        const float xi = xs[row], si = ssq[row];
        float4 o0, o1;
        o0.x = xi * xj[0] - si * sj[0];  o1.x = si * xj[0] - xi * sj[0];
        o0.y = xi * xj[1] - si * sj[1];  o1.y = si * xj[1] - xi * sj[1];
        o0.z = xi * xj[2] - si * sj[2];  o1.z = si * xj[2] - xi * sj[2];
        o0.w = xi * xj[3] - si * sj[3];  o1.w = si * xj[3] - xi * sj[3];
        *(float4*)(g0 + row * SS + c0) = o0;
        *(float4*)(g1 + row * SS + c0) = o1;
    }
}

// ---------------- L1 direct conv (FFMA2), NCHW in -> NHWC out (tf32-rounded) --------
__global__ void __launch_bounds__(128)
conv1_ffma2(const float* __restrict__ in, const float* __restrict__ Wr,
            const float* __restrict__ bias, float* __restrict__ out)
{
    constexpr int CIN = 2, HIN = 128, COUT = 32, HOUT = 64, WQ = 16;
    const int tid  = threadIdx.x;
    const int sid  = tid + blockIdx.z * 128;
    const int n    = blockIdx.x;
    const int cout0 = blockIdx.y * 8;
    const int oh  = sid / WQ;
    const int ow0 = (sid % WQ) * 4;

    const float* __restrict__ inN = in + (size_t)n * CIN * HIN * HIN;

    unsigned long long acc[4][4];
    #pragma unroll
    for (int cp = 0; cp < 4; cp++)
        #pragma unroll
        for (int o = 0; o < 4; o++) acc[cp][o] = 0ull;

    const bool rguard = (ow0 * 2 + 8 < HIN);

    #pragma unroll
    for (int ci = 0; ci < CIN; ci++) {
        const float* __restrict__ wbase = Wr + ((size_t)ci * 9) * COUT + cout0;
        const float* __restrict__ inC = inN + (size_t)ci * HIN * HIN;
        #pragma unroll
        for (int kh = 0; kh < 3; kh++) {
            const int ih = oh * 2 + kh;
            if (ih >= HIN) break;
            const float* row = inC + (size_t)ih * HIN + ow0 * 2;
            float r[9];
            const float4 a = *(const float4*)row;
            const float4 b = *(const float4*)(row + 4);
            r[0]=a.x; r[1]=a.y; r[2]=a.z; r[3]=a.w;
            r[4]=b.x; r[5]=b.y; r[6]=b.z; r[7]=b.w;
            r[8] = rguard ? row[8] : 0.0f;
            unsigned long long pb[9];
            #pragma unroll
            for (int v = 0; v < 9; v++) pb[v] = pk2(r[v], r[v]);
            #pragma unroll
            for (int kw = 0; kw < 3; kw++) {
                const float* wp = wbase + (kh * 3 + kw) * COUT;
                const ulonglong2 wa = *(const ulonglong2*)(wp);
                const ulonglong2 wb = *(const ulonglong2*)(wp + 4);
                #pragma unroll
                for (int o = 0; o < 4; o++) {
                    const unsigned long long x = pb[2 * o + kw];
                    fma2(acc[0][o], wa.x, x);
                    fma2(acc[1][o], wa.y, x);
                    fma2(acc[2][o], wb.x, x);
                    fma2(acc[3][o], wb.y, x);
                }
            }
        }
    }

    float bv[8];
    #pragma unroll
    for (int c = 0; c < 8; c++) bv[c] = __ldg(bias + cout0 + c);
    #pragma unroll
    for (int o = 0; o < 4; o++) {
        float l0,h0,l1,h1,l2,h2,l3,h3;
        upk2(acc[0][o], l0, h0); upk2(acc[1][o], l1, h1);
        upk2(acc[2][o], l2, h2); upk2(acc[3][o], l3, h3);
        float4 vlo, vhi;   // tf32-round outputs so downstream MMA truncation is exact
        vlo.x = f2tf32f(fmaxf(l0 + bv[0], 0.f)); vlo.y = f2tf32f(fmaxf(h0 + bv[1], 0.f));
        vlo.z = f2tf32f(fmaxf(l1 + bv[2], 0.f)); vlo.w = f2tf32f(fmaxf(h1 + bv[3], 0.f));
        vhi.x = f2tf32f(fmaxf(l2 + bv[4], 0.f)); vhi.y = f2tf32f(fmaxf(h2 + bv[5], 0.f));
        vhi.z = f2tf32f(fmaxf(l3 + bv[6], 0.f)); vhi.w = f2tf32f(fmaxf(h3 + bv[7], 0.f));
        float* op = out + (((size_t)n * HOUT + oh) * HOUT + (ow0 + o)) * COUT + cout0;
        *(float4*)op = vlo;
        *(float4*)(op + 4) = vhi;
    }
}

// ---------------- tf32 mma.sync implicit-GEMM conv, 2-stage cp.async, 2 CTAs/SM -----
// in: NHWC (tf32-rounded); Br: [k][COUT] tf32 bits; out: NHWC.
// CTA 256 thr, tile M=TM x N=COUT, K chunks of 32, double-buffered.
// Warp grid WM x WN (8 warps); warp tile (TM/WM) x (COUT/WN).
template<int CIN, int HIN, int COUT, int TM, int WM, int WN, bool CVTOUT>
__global__ void __launch_bounds__(256, 2)
conv_mma(const float* __restrict__ in, const float* __restrict__ Br,
         const float* __restrict__ bias, float* __restrict__ out)
{
    static_assert(WM * WN == 8, "8 warps");
    constexpr int HOUT = HIN / 2;
    constexpr int P    = HOUT * HOUT;
    constexpr int K    = CIN * 9;
    constexpr int NCH  = K / 32;
    constexpr int CPT  = CIN / 32;
    constexpr int MF   = TM / (WM * 16);   // m fragments per warp
    constexpr int WNT  = COUT / WN;        // warp n-tile
    constexpr int NF   = WNT / 8;          // n fragments per warp
    constexpr int AST  = 36;               // A smem row stride (floats)
    constexpr int BST  = COUT + 8;         // B smem row stride (floats), ≡8 mod 32
    constexpr int AFL  = TM * AST;
    constexpr int BFL  = 32 * BST;
    constexpr int SFL  = AFL + BFL;        // floats per stage
    constexpr int TPR  = 256 / TM;         // threads per A row
    constexpr int CHK  = 8 / TPR;          // 16B chunks per thread

    extern __shared__ float smf[];
    const uint32_t sm0 = smem_u32(smf);

    const int tid  = threadIdx.x;
    const int lane = tid & 31;
    const int wid  = tid >> 5;
    const int wm   = wid % WM;
    const int wn   = wid / WM;
    const int g    = lane >> 2;           // 0..7
    const int tq   = lane & 3;            // 0..3

    // A staging coords
    const int r    = tid / TPR;
    const int sub  = tid % TPR;
    const int pos  = blockIdx.x * TM + r;
    const int nimg = pos / P;
    const int rem  = pos % P;
    const int oh   = rem / HOUT, ow = rem % HOUT;

    const uint32_t a_dst_off = (uint32_t)(r * AST + sub * CHK * 4) * 4;

    auto prefetch = [&](int kc, int slot) {
        const uint32_t sbase = sm0 + (uint32_t)(slot * SFL) * 4;
        const int t   = kc / CPT;
        const int ci0 = (kc % CPT) * 32;
        const int kh = t / 3, kw = t % 3;
        const int ih = oh * 2 + kh, iw = ow * 2 + kw;
        const bool val = (ih < HIN) && (iw < HIN);
        const float* s = val
            ? in + ((((size_t)nimg * HIN + ih) * HIN + iw) * CIN + ci0) + sub * CHK * 4
            : in;
        const int sz = val ? 16 : 0;
        const uint32_t ad = sbase + a_dst_off;
        #pragma unroll
        for (int c = 0; c < CHK; c++)
            cpasync16(ad + c * 16, s + c * 4, sz);
        // B: 32 rows x COUT floats
        const float* bsrc = Br + (size_t)(kc * 32) * COUT;
        const uint32_t bd = sbase + (uint32_t)AFL * 4;
        #pragma unroll
        for (int j = 0; j < COUT / 32; j++) {
            const int cid = j * 256 + tid;
            const int k   = cid / (COUT / 4);
            const int cc  = cid % (COUT / 4);
            cpasync16(bd + (uint32_t)(k * BST + cc * 4) * 4, bsrc + (size_t)k * COUT + cc * 4, 16);
        }
    };

    prefetch(0, 0); CP_COMMIT();

    float d[MF][NF][4];
    #pragma unroll
    for (int mf = 0; mf < MF; mf++)
        #pragma unroll
        for (int nf = 0; nf < NF; nf++)
            #pragma unroll
            for (int j = 0; j < 4; j++) d[mf][nf][j] = 0.f;

    for (int c = 0; c < NCH; c++) {
        const int buf = c & 1;
        if (c + 1 < NCH) {
            prefetch(c + 1, buf ^ 1);   // safe: trailing sync of iter c-1 drained readers
            CP_COMMIT();
            CP_WAIT1();
        } else {
            CP_WAIT0();
        }
        __syncthreads();

        const uint32_t* A = (const uint32_t*)(smf + buf * SFL);
        const uint32_t* B = A + AFL;
        #pragma unroll
        for (int ks = 0; ks < 4; ks++) {
            uint32_t a[MF][4], b[NF][2];
            const int ac = ks * 8 + tq;
            #pragma unroll
            for (int mf = 0; mf < MF; mf++) {
                const int ar = wm * (16 * MF) + mf * 16 + g;
                a[mf][0] = A[ar * AST + ac];
                a[mf][1] = A[(ar + 8) * AST + ac];
                a[mf][2] = A[ar * AST + ac + 4];
                a[mf][3] = A[(ar + 8) * AST + ac + 4];
            }
            const int bkr = ks * 8 + tq;
            #pragma unroll
            for (int nf = 0; nf < NF; nf++) {
                const int bcc = wn * WNT + nf * 8 + g;
                b[nf][0] = B[bkr * BST + bcc];
                b[nf][1] = B[(bkr + 4) * BST + bcc];
            }
            #pragma unroll
            for (int mf = 0; mf < MF; mf++)
                #pragma unroll
                for (int nf = 0; nf < NF; nf++)
                    mma_tf32(d[mf][nf], a[mf], b[nf]);
        }
        __syncthreads();
    }

    // epilogue: bias + ReLU (+ optional tf32 round), NHWC float2 stores
    #pragma unroll
    for (int nf = 0; nf < NF; nf++) {
        const int col = wn * WNT + nf * 8 + 2 * tq;
        const float b0 = __ldg(bias + col);
        const float b1 = __ldg(bias + col + 1);
        #pragma unroll
        for (int mf = 0; mf < MF; mf++) {
            const int row0 = blockIdx.x * TM + wm * (16 * MF) + mf * 16 + g;
            float2 v0, v1;
            v0.x = fmaxf(d[mf][nf][0] + b0, 0.f);
            v0.y = fmaxf(d[mf][nf][1] + b1, 0.f);
            v1.x = fmaxf(d[mf][nf][2] + b0, 0.f);
            v1.y = fmaxf(d[mf][nf][3] + b1, 0.f);
            if (CVTOUT) {
                v0.x = f2tf32f(v0.x); v0.y = f2tf32f(v0.y);
                v1.x = f2tf32f(v1.x); v1.y = f2tf32f(v1.y);
            }
            *(float2*)(out + (size_t)row0 * COUT + col)       = v0;
            *(float2*)(out + (size_t)(row0 + 8) * COUT + col) = v1;
        }
    }
}

// ---------------- pool stage 1: per image, sum 64 positions ----------------
__global__ void pool1()
{
    const int img = blockIdx.x;
    const int k = threadIdx.x;  // 0..255
    const float* __restrict__ base = g_h4 + (size_t)img * 64 * 256 + k;
    float s = 0.0f;
    #pragma unroll
    for (int i = 0; i < 64; i++)
        s += base[(size_t)i * 256];
    g_pp[img * 256 + k] = s;
}
// ---------------- pool stage 2: sum over C=32 heads ----------------
__global__ void pool2()
{
    const int b = blockIdx.x;
    const int k = threadIdx.x;
    const float* __restrict__ p = g_pp + (size_t)b * 32 * 256 + k;
    float s = 0.0f;
    #pragma unroll
    for (int c = 0; c < 32; c++)
        s += p[(size_t)c * 256];
    g_pbar[b * 256 + k] = s * (1.0f / 2048.0f);
}

// ---------------- FC ----------------
__global__ void fc_kernel(const float* __restrict__ Wfc, const float* __restrict__ bfc,
                          float* __restrict__ out)
{
    const int b = blockIdx.x;
    const int l = threadIdx.x;
    float s = bfc[l];
    const float* p = g_pbar + b * 256;
    #pragma unroll 8
    for (int k = 0; k < 256; k++)
        s = fmaf(p[k], Wfc[k * LATENT + l], s);
    out[b * LATENT + l] = s;
}

// ---------------- launch ----------------
extern "C" void kernel_launch(void* const* d_in, const int* in_sizes, int n_in,
                              void* d_out, int out_size)
{
    const float* x_raw = (const float*)d_in[0];
    const float* W1 = (const float*)d_in[1];  const float* b1 = (const float*)d_in[2];
    const float* W2 = (const float*)d_in[3];  const float* b2 = (const float*)d_in[4];
    const float* W3 = (const float*)d_in[5];  const float* b3 = (const float*)d_in[6];
    const float* W4 = (const float*)d_in[7];  const float* b4 = (const float*)d_in[8];
    const float* Wfc = (const float*)d_in[9]; const float* bfc = (const float*)d_in[10];
    float* out = (float*)d_out;

    float *gaf, *h1, *h2, *h3, *h4, *wr1, *wr2, *wr3, *wr4;
    cudaGetSymbolAddress((void**)&gaf, g_gaf);
    cudaGetSymbolAddress((void**)&h1, g_h1);
    cudaGetSymbolAddress((void**)&h2, g_h2);
    cudaGetSymbolAddress((void**)&h3, g_h3);
    cudaGetSymbolAddress((void**)&h4, g_h4);
    cudaGetSymbolAddress((void**)&wr1, g_wr1);
    cudaGetSymbolAddress((void**)&wr2, g_wr2);
    cudaGetSymbolAddress((void**)&wr3, g_wr3);
    cudaGetSymbolAddress((void**)&wr4, g_wr4);

    // 2 stages of (A + B) floats -> 2 CTAs/SM
    const int smem2 = 2 * (256 * 36 + 32 * 72)  * 4;   // 92160
    const int smem3 = 2 * (128 * 36 + 32 * 136) * 4;   // 71680
    const int smem4 = 2 * (64  * 36 + 32 * 264) * 4;   // 86016
    cudaFuncSetAttribute((const void*)conv_mma<32, 64, 64, 256, 4, 2, true>,
                         cudaFuncAttributeMaxDynamicSharedMemorySize, smem2);
    cudaFuncSetAttribute((const void*)conv_mma<64, 32, 128, 128, 2, 4, true>,
                         cudaFuncAttributeMaxDynamicSharedMemorySize, smem3);
    cudaFuncSetAttribute((const void*)conv_mma<128, 16, 256, 64, 2, 4, false>,
                         cudaFuncAttributeMaxDynamicSharedMemorySize, smem4);

    const int rp_total = 576 + 288 * 64 + 576 * 128 + 1152 * 256;

    repack_all<<<(rp_total + 255) / 256, 256>>>(W1, W2, W3, W4);       // 0
    gaf_kernel<<<NIMG, 128>>>(x_raw);                                  // 1
    conv1_ffma2<<<dim3(NIMG, 4, 8), 128>>>(gaf, wr1, b1, h1);          // 2
    conv_mma<32, 64, 64, 256, 4, 2, true>  <<<NIMG * 1024 / 256, 256, smem2>>>(h1, wr2, b2, h2);  // 3
    conv_mma<64, 32, 128, 128, 2, 4, true> <<<NIMG * 256  / 128, 256, smem3>>>(h2, wr3, b3, h3);  // 4
    conv_mma<128, 16, 256, 64, 2, 4, false><<<NIMG * 64   / 64,  256, smem4>>>(h3, wr4, b4, h4);  // 5
    pool1<<<NIMG, 256>>>();                                            // 6
    pool2<<<BB, 256>>>();                                              // 7
    fc_kernel<<<BB, LATENT>>>(Wfc, bfc, out);                          // 8
}

// round 10
// speedup vs baseline: 1.2249x; 1.2249x over previous
#include <cuda_runtime.h>
#include <cstdint>
#include <math.h>

// Problem constants
#define BB 16
#define CC 32
#define TT 512
#define SS 128       // GAF_SIZE
#define NIMG (BB*CC) // 512
#define LATENT 128

// k-perm within groups of 8: storage pos(j) = (j%4)*2 + j/4  -> [0,4,1,5,2,6,3,7]
// inverse: logical(p) = (p%2)*4 + p/2

// ---------------- scratch (no allocation allowed) ----------------
__device__ float g_gaf[(size_t)NIMG * 2 * SS * SS];      // NCHW (input to L1)
__device__ float g_h1 [(size_t)NIMG * 64 * 64 * 32];     // NHWC, tf32, ch-permuted
__device__ float g_h2 [(size_t)NIMG * 32 * 32 * 64];     // NHWC, tf32, ch-permuted
__device__ float g_h3 [(size_t)NIMG * 16 * 16 * 128];    // NHWC, tf32, ch-permuted
__device__ float g_h4 [(size_t)NIMG * 8 * 8 * 256];      // NHWC, fp32, UNpermuted
__device__ float g_pp  [NIMG * 256];
__device__ float g_pbar[BB * 256];
__device__ float g_wr1[2 * 9 * 32];                      // L1: [ci][t][cout]
__device__ float g_wr2[(32 * 9)  * 64];                  // [k'][cout], tf32 bits, k' perm
__device__ float g_wr3[(64 * 9)  * 128];
__device__ float g_wr4[(128 * 9) * 256];

// ---------------- helpers ----------------
__device__ __forceinline__ uint32_t f2tf32(float f) {
    uint32_t o;
    asm("cvt.rna.tf32.f32 %0, %1;" : "=r"(o) : "f"(f));
    return o;
}
__device__ __forceinline__ float f2tf32f(float f) {
    return __uint_as_float(f2tf32(f));
}
__device__ __forceinline__ void mma_tf32(float* d, const uint32_t* a, const uint32_t* b) {
    asm volatile(
        "mma.sync.aligned.m16n8k8.row.col.f32.tf32.tf32.f32 "
        "{%0,%1,%2,%3}, {%4,%5,%6,%7}, {%8,%9}, {%0,%1,%2,%3};"
        : "+f"(d[0]), "+f"(d[1]), "+f"(d[2]), "+f"(d[3])
        : "r"(a[0]), "r"(a[1]), "r"(a[2]), "r"(a[3]), "r"(b[0]), "r"(b[1]));
}
__device__ __forceinline__ uint32_t smem_u32(const void* p) {
    uint32_t a;
    asm("{ .reg .u64 t; cvta.to.shared.u64 t, %1; cvt.u32.u64 %0, t; }" : "=r"(a) : "l"(p));
    return a;
}
__device__ __forceinline__ void cpasync16(uint32_t dst, const void* src, int srcsize) {
    asm volatile("cp.async.cg.shared.global [%0], [%1], 16, %2;"
                 :: "r"(dst), "l"(src), "r"(srcsize) : "memory");
}
#define CP_COMMIT() asm volatile("cp.async.commit_group;" ::: "memory")
#define CP_WAIT1()  asm volatile("cp.async.wait_group 1;" ::: "memory")
#define CP_WAIT0()  asm volatile("cp.async.wait_group 0;" ::: "memory")

// ---------------- f32x2 helpers (L1 conv) ----------------
__device__ __forceinline__ unsigned long long pk2(float a, float b) {
    unsigned long long r;
    asm("mov.b64 %0, {%1, %2};" : "=l"(r) : "f"(a), "f"(b));
    return r;
}
__device__ __forceinline__ void upk2(unsigned long long v, float& a, float& b) {
    asm("mov.b64 {%0, %1}, %2;" : "=f"(a), "=f"(b) : "l"(v));
}
__device__ __forceinline__ void fma2(unsigned long long& d, unsigned long long a, unsigned long long b) {
    asm("fma.rn.f32x2 %0, %1, %2, %3;" : "=l"(d) : "l"(a), "l"(b), "l"(d));
}

// ---------------- merged weight repack (k' index is storage/permuted) -------------
__device__ __forceinline__ void rp_tc(const float* __restrict__ W, uint32_t* __restrict__ Br,
                                      int CIN, int COUT, int idx)
{
    int co = idx % COUT;
    int kp = idx / COUT;              // storage k'
    int t  = kp / CIN;
    int rp = kp % CIN;
    int p  = rp & 7;
    int ci = (rp & ~7) | ((p & 1) * 4 + (p >> 1));   // logical ci (inverse perm)
    Br[idx] = f2tf32(W[((size_t)co * CIN + ci) * 9 + t]);
}
__global__ void repack_all(const float* __restrict__ W1, const float* __restrict__ W2,
                           const float* __restrict__ W3, const float* __restrict__ W4)
{
    int idx = blockIdx.x * blockDim.x + threadIdx.x;
    if (idx < 576) {                       // L1: W[32][2][3][3] -> [ci][t][cout] (no perm)
        int co = idx % 32;
        int t  = (idx / 32) % 9;
        int ci = idx / (32 * 9);
        g_wr1[idx] = W1[((size_t)co * 2 + ci) * 9 + t];
        return;
    }
    idx -= 576;
    if (idx < 288 * 64)  { rp_tc(W2, (uint32_t*)g_wr2, 32, 64, idx);  return; }
    idx -= 288 * 64;
    if (idx < 576 * 128) { rp_tc(W3, (uint32_t*)g_wr3, 64, 128, idx); return; }
    idx -= 576 * 128;
    if (idx < 1152 * 256) rp_tc(W4, (uint32_t*)g_wr4, 128, 256, idx);
}

// ---------------- GAF kernel (NCHW out), coalesced row stores ----------------
__global__ void gaf_kernel(const float* __restrict__ x_raw)
{
    const int img = blockIdx.x;
    const int tid = threadIdx.x;   // 0..127
    __shared__ float xs[SS];
    __shared__ float ssq[SS];
    __shared__ float smn[4], smx[4];

    const float4 v4 = *(const float4*)(x_raw + (size_t)img * TT + tid * 4);
    float v = 0.25f * (v4.x + v4.y + v4.z + v4.w);

    float mn = v, mx = v;
    #pragma unroll
    for (int o = 16; o > 0; o >>= 1) {
        mn = fminf(mn, __shfl_xor_sync(0xffffffffu, mn, o));
        mx = fmaxf(mx, __shfl_xor_sync(0xffffffffu, mx, o));
    }
    const int warp = tid >> 5, lane = tid & 31;
    if (lane == 0) { smn[warp] = mn; smx[warp] = mx; }
    __syncthreads();
    mn = fminf(fminf(smn[0], smn[1]), fminf(smn[2], smn[3]));
    mx = fmaxf(fmaxf(smx[0], smx[1]), fmaxf(smx[2], smx[3]));

    float xn = 2.0f * (v - mn) / (mx - mn + 1e-8f) - 1.0f;
    xn = fminf(1.0f, fmaxf(-1.0f, xn));
    float sq = sqrtf(fminf(1.0f, fmaxf(0.0f, 1.0f - xn * xn)));
    xs[tid] = xn;
    ssq[tid] = sq;
    __syncthreads();

    const int c0 = lane * 4;
    float xj[4], sj[4];
    #pragma unroll
    for (int c = 0; c < 4; c++) { xj[c] = xs[c0 + c]; sj[c] = ssq[c0 + c]; }
    float* __restrict__ g0 = g_gaf + (size_t)img * (2 * SS * SS);
    float* __restrict__ g1 = g0 + SS * SS;
    for (int rb = 0; rb < SS; rb += 4) {
        const int row = rb + warp;
        const float xi = xs[row], si = ssq[row];
        float4 o0, o1;
        o0.x = xi * xj[0] - si * sj[0];  o1.x = si * xj[0] - xi * sj[0];
        o0.y = xi * xj[1] - si * sj[1];  o1.y = si * xj[1] - xi * sj[1];
        o0.z = xi * xj[2] - si * sj[2];  o1.z = si * xj[2] - xi * sj[2];
        o0.w = xi * xj[3] - si * sj[3];  o1.w = si * xj[3] - xi * sj[3];
        *(float4*)(g0 + row * SS + c0) = o0;
        *(float4*)(g1 + row * SS + c0) = o1;
    }
}

// ---------------- L1 direct conv (FFMA2), NCHW in -> NHWC out (tf32, permuted) ------
__global__ void __launch_bounds__(128)
conv1_ffma2(const float* __restrict__ in, const float* __restrict__ Wr,
            const float* __restrict__ bias, float* __restrict__ out)
{
    constexpr int CIN = 2, HIN = 128, COUT = 32, HOUT = 64, WQ = 16;
    const int tid  = threadIdx.x;
    const int sid  = tid + blockIdx.z * 128;
    const int n    = blockIdx.x;
    const int cout0 = blockIdx.y * 8;
    const int oh  = sid / WQ;
    const int ow0 = (sid % WQ) * 4;

    const float* __restrict__ inN = in + (size_t)n * CIN * HIN * HIN;

    unsigned long long acc[4][4];
    #pragma unroll
    for (int cp = 0; cp < 4; cp++)
        #pragma unroll
        for (int o = 0; o < 4; o++) acc[cp][o] = 0ull;

    const bool rguard = (ow0 * 2 + 8 < HIN);

    #pragma unroll
    for (int ci = 0; ci < CIN; ci++) {
        const float* __restrict__ wbase = Wr + ((size_t)ci * 9) * COUT + cout0;
        const float* __restrict__ inC = inN + (size_t)ci * HIN * HIN;
        #pragma unroll
        for (int kh = 0; kh < 3; kh++) {
            const int ih = oh * 2 + kh;
            if (ih >= HIN) break;
            const float* row = inC + (size_t)ih * HIN + ow0 * 2;
            float r[9];
            const float4 a = *(const float4*)row;
            const float4 b = *(const float4*)(row + 4);
            r[0]=a.x; r[1]=a.y; r[2]=a.z; r[3]=a.w;
            r[4]=b.x; r[5]=b.y; r[6]=b.z; r[7]=b.w;
            r[8] = rguard ? row[8] : 0.0f;
            unsigned long long pb[9];
            #pragma unroll
            for (int v = 0; v < 9; v++) pb[v] = pk2(r[v], r[v]);
            #pragma unroll
            for (int kw = 0; kw < 3; kw++) {
                const float* wp = wbase + (kh * 3 + kw) * COUT;
                const ulonglong2 wa = *(const ulonglong2*)(wp);
                const ulonglong2 wb = *(const ulonglong2*)(wp + 4);
                #pragma unroll
                for (int o = 0; o < 4; o++) {
                    const unsigned long long x = pb[2 * o + kw];
                    fma2(acc[0][o], wa.x, x);
                    fma2(acc[1][o], wa.y, x);
                    fma2(acc[2][o], wb.x, x);
                    fma2(acc[3][o], wb.y, x);
                }
            }
        }
    }

    float bv[8];
    #pragma unroll
    for (int c = 0; c < 8; c++) bv[c] = __ldg(bias + cout0 + c);
    #pragma unroll
    for (int o = 0; o < 4; o++) {
        float val[8];
        upk2(acc[0][o], val[0], val[1]); upk2(acc[1][o], val[2], val[3]);
        upk2(acc[2][o], val[4], val[5]); upk2(acc[3][o], val[6], val[7]);
        #pragma unroll
        for (int c = 0; c < 8; c++) val[c] = f2tf32f(fmaxf(val[c] + bv[c], 0.f));
        // permuted channel order [0,4,1,5,2,6,3,7]
        float4 vlo, vhi;
        vlo.x = val[0]; vlo.y = val[4]; vlo.z = val[1]; vlo.w = val[5];
        vhi.x = val[2]; vhi.y = val[6]; vhi.z = val[3]; vhi.w = val[7];
        float* op = out + (((size_t)n * HOUT + oh) * HOUT + (ow0 + o)) * COUT + cout0;
        *(float4*)op = vlo;
        *(float4*)(op + 4) = vhi;
    }
}

// ---------------- tf32 mma.sync implicit-GEMM conv, 3-stage cp.async, k-perm --------
// in: NHWC (tf32, ch-permuted); Br: [k'][COUT] tf32 bits (k' permuted); out: NHWC.
// A-fragment cols (tq, tq+4) are adjacent in storage -> LDS.64.
template<int CIN, int HIN, int COUT, int TM, int WM, int WN, bool CVTOUT>
__global__ void __launch_bounds__(256)
conv_mma(const float* __restrict__ in, const float* __restrict__ Br,
         const float* __restrict__ bias, float* __restrict__ out)
{
    static_assert(WM * WN == 8, "8 warps");
    constexpr int HOUT = HIN / 2;
    constexpr int P    = HOUT * HOUT;
    constexpr int K    = CIN * 9;
    constexpr int NCH  = K / 32;
    constexpr int CPT  = CIN / 32;
    constexpr int MF   = TM / (WM * 16);   // m fragments per warp
    constexpr int WNT  = COUT / WN;        // warp n-tile
    constexpr int NF   = WNT / 8;          // n fragments per warp
    constexpr int AST  = 36;               // A smem row stride (floats)
    constexpr int BST  = COUT + 8;         // B smem row stride (floats)
    constexpr int AFL  = TM * AST;
    constexpr int BFL  = 32 * BST;
    constexpr int SFL  = AFL + BFL;        // floats per stage
    constexpr int TPR  = 256 / TM;         // threads per A row
    constexpr int CHK  = 8 / TPR;          // 16B chunks per thread

    extern __shared__ float smf[];
    const uint32_t sm0 = smem_u32(smf);

    const int tid  = threadIdx.x;
    const int lane = tid & 31;
    const int wid  = tid >> 5;
    const int wm   = wid % WM;
    const int wn   = wid / WM;
    const int g    = lane >> 2;           // 0..7
    const int tq   = lane & 3;            // 0..3

    // A staging coords
    const int r    = tid / TPR;
    const int sub  = tid % TPR;
    const int pos  = blockIdx.x * TM + r;
    const int nimg = pos / P;
    const int rem  = pos % P;
    const int oh   = rem / HOUT, ow = rem % HOUT;

    const uint32_t a_dst_off = (uint32_t)(r * AST + sub * CHK * 4) * 4;

    auto prefetch = [&](int kc, int slot) {
        const uint32_t sbase = sm0 + (uint32_t)(slot * SFL) * 4;
        const int t   = kc / CPT;
        const int ci0 = (kc % CPT) * 32;
        const int kh = t / 3, kw = t % 3;
        const int ih = oh * 2 + kh, iw = ow * 2 + kw;
        const bool val = (ih < HIN) && (iw < HIN);
        const float* s = val
            ? in + ((((size_t)nimg * HIN + ih) * HIN + iw) * CIN + ci0) + sub * CHK * 4
            : in;
        const int sz = val ? 16 : 0;
        const uint32_t ad = sbase + a_dst_off;
        #pragma unroll
        for (int c = 0; c < CHK; c++)
            cpasync16(ad + c * 16, s + c * 4, sz);
        // B: 32 rows x COUT floats
        const float* bsrc = Br + (size_t)(kc * 32) * COUT;
        const uint32_t bd = sbase + (uint32_t)AFL * 4;
        #pragma unroll
        for (int j = 0; j < COUT / 32; j++) {
            const int cid = j * 256 + tid;
            const int k   = cid / (COUT / 4);
            const int cc  = cid % (COUT / 4);
            cpasync16(bd + (uint32_t)(k * BST + cc * 4) * 4, bsrc + (size_t)k * COUT + cc * 4, 16);
        }
    };

    prefetch(0, 0); CP_COMMIT();
    prefetch(1, 1); CP_COMMIT();

    float d[MF][NF][4];
    #pragma unroll
    for (int mf = 0; mf < MF; mf++)
        #pragma unroll
        for (int nf = 0; nf < NF; nf++)
            #pragma unroll
            for (int j = 0; j < 4; j++) d[mf][nf][j] = 0.f;

    int slot = 0;
    for (int c = 0; c < NCH; c++) {
        if (c + 1 < NCH) { CP_WAIT1(); } else { CP_WAIT0(); }
        __syncthreads();
        if (c + 2 < NCH) {
            int ps = slot + 2; if (ps >= 3) ps -= 3;
            prefetch(c + 2, ps);
            CP_COMMIT();
        }

        const float*    Af = smf + slot * SFL;
        const uint32_t* B  = (const uint32_t*)(Af + AFL);
        #pragma unroll
        for (int ks = 0; ks < 4; ks++) {
            uint32_t a[MF][4], b[NF][2];
            const int ac = ks * 8 + 2 * tq;   // storage cols (logical tq, tq+4)
            #pragma unroll
            for (int mf = 0; mf < MF; mf++) {
                const int ar = wm * (16 * MF) + mf * 16 + g;
                const float2 lo = *(const float2*)(Af + ar * AST + ac);
                const float2 hi = *(const float2*)(Af + (ar + 8) * AST + ac);
                a[mf][0] = __float_as_uint(lo.x);
                a[mf][2] = __float_as_uint(lo.y);
                a[mf][1] = __float_as_uint(hi.x);
                a[mf][3] = __float_as_uint(hi.y);
            }
            const int bkr = ks * 8 + 2 * tq;  // storage rows (logical tq, tq+4)
            #pragma unroll
            for (int nf = 0; nf < NF; nf++) {
                const int bcc = wn * WNT + nf * 8 + g;
                b[nf][0] = B[bkr * BST + bcc];
                b[nf][1] = B[(bkr + 1) * BST + bcc];
            }
            #pragma unroll
            for (int mf = 0; mf < MF; mf++)
                #pragma unroll
                for (int nf = 0; nf < NF; nf++)
                    mma_tf32(d[mf][nf], a[mf], b[nf]);
        }
        if (++slot == 3) slot = 0;
    }

    // epilogue: bias + ReLU; CVTOUT layers write channel-permuted tf32 (scalar stores),
    // final layer writes unpermuted fp32 (float2 stores).
    #pragma unroll
    for (int nf = 0; nf < NF; nf++) {
        const int col = wn * WNT + nf * 8 + 2 * tq;   // logical col (even)
        const float b0 = __ldg(bias + col);
        const float b1 = __ldg(bias + col + 1);
        const int base = col & ~7;
        const int q0 = col & 7, q1 = q0 + 1;
        const int p0 = (q0 & 3) * 2 + (q0 >> 2);      // pos(even)
        const int p1 = (q1 & 3) * 2 + (q1 >> 2);      // pos(odd)
        #pragma unroll
        for (int mf = 0; mf < MF; mf++) {
            const int row0 = blockIdx.x * TM + wm * (16 * MF) + mf * 16 + g;
            float v00 = fmaxf(d[mf][nf][0] + b0, 0.f);
            float v01 = fmaxf(d[mf][nf][1] + b1, 0.f);
            float v10 = fmaxf(d[mf][nf][2] + b0, 0.f);
            float v11 = fmaxf(d[mf][nf][3] + b1, 0.f);
            if (CVTOUT) {
                float* o0 = out + (size_t)row0 * COUT + base;
                float* o1 = out + (size_t)(row0 + 8) * COUT + base;
                o0[p0] = f2tf32f(v00); o0[p1] = f2tf32f(v01);
                o1[p0] = f2tf32f(v10); o1[p1] = f2tf32f(v11);
            } else {
                *(float2*)(out + (size_t)row0 * COUT + col)       = make_float2(v00, v01);
                *(float2*)(out + (size_t)(row0 + 8) * COUT + col) = make_float2(v10, v11);
            }
        }
    }
}

// ---------------- pool stage 1: per image, sum 64 positions ----------------
__global__ void pool1()
{
    const int img = blockIdx.x;
    const int k = threadIdx.x;  // 0..255
    const float* __restrict__ base = g_h4 + (size_t)img * 64 * 256 + k;
    float s = 0.0f;
    #pragma unroll
    for (int i = 0; i < 64; i++)
        s += base[(size_t)i * 256];
    g_pp[img * 256 + k] = s;
}
// ---------------- pool stage 2: sum over C=32 heads ----------------
__global__ void pool2()
{
    const int b = blockIdx.x;
    const int k = threadIdx.x;
    const float* __restrict__ p = g_pp + (size_t)b * 32 * 256 + k;
    float s = 0.0f;
    #pragma unroll
    for (int c = 0; c < 32; c++)
        s += p[(size_t)c * 256];
    g_pbar[b * 256 + k] = s * (1.0f / 2048.0f);
}

// ---------------- FC ----------------
__global__ void fc_kernel(const float* __restrict__ Wfc, const float* __restrict__ bfc,
                          float* __restrict__ out)
{
    const int b = blockIdx.x;
    const int l = threadIdx.x;
    float s = bfc[l];
    const float* p = g_pbar + b * 256;
    #pragma unroll 8
    for (int k = 0; k < 256; k++)
        s = fmaf(p[k], Wfc[k * LATENT + l], s);
    out[b * LATENT + l] = s;
}

// ---------------- launch ----------------
extern "C" void kernel_launch(void* const* d_in, const int* in_sizes, int n_in,
                              void* d_out, int out_size)
{
    const float* x_raw = (const float*)d_in[0];
    const float* W1 = (const float*)d_in[1];  const float* b1 = (const float*)d_in[2];
    const float* W2 = (const float*)d_in[3];  const float* b2 = (const float*)d_in[4];
    const float* W3 = (const float*)d_in[5];  const float* b3 = (const float*)d_in[6];
    const float* W4 = (const float*)d_in[7];  const float* b4 = (const float*)d_in[8];
    const float* Wfc = (const float*)d_in[9]; const float* bfc = (const float*)d_in[10];
    float* out = (float*)d_out;

    float *gaf, *h1, *h2, *h3, *h4, *wr1, *wr2, *wr3, *wr4;
    cudaGetSymbolAddress((void**)&gaf, g_gaf);
    cudaGetSymbolAddress((void**)&h1, g_h1);
    cudaGetSymbolAddress((void**)&h2, g_h2);
    cudaGetSymbolAddress((void**)&h3, g_h3);
    cudaGetSymbolAddress((void**)&h4, g_h4);
    cudaGetSymbolAddress((void**)&wr1, g_wr1);
    cudaGetSymbolAddress((void**)&wr2, g_wr2);
    cudaGetSymbolAddress((void**)&wr3, g_wr3);
    cudaGetSymbolAddress((void**)&wr4, g_wr4);

    // 3 stages of (A + B) floats
    const int smem2 = 3 * (256 * 36 + 32 * 72)  * 4;   // 138240
    const int smem3 = 3 * (128 * 36 + 32 * 136) * 4;   // 107520
    const int smem4 = 3 * (64  * 36 + 32 * 264) * 4;   // 129024
    cudaFuncSetAttribute((const void*)conv_mma<32, 64, 64, 256, 4, 2, true>,
                         cudaFuncAttributeMaxDynamicSharedMemorySize, smem2);
    cudaFuncSetAttribute((const void*)conv_mma<64, 32, 128, 128, 2, 4, true>,
                         cudaFuncAttributeMaxDynamicSharedMemorySize, smem3);
    cudaFuncSetAttribute((const void*)conv_mma<128, 16, 256, 64, 2, 4, false>,
                         cudaFuncAttributeMaxDynamicSharedMemorySize, smem4);

    const int rp_total = 576 + 288 * 64 + 576 * 128 + 1152 * 256;

    repack_all<<<(rp_total + 255) / 256, 256>>>(W1, W2, W3, W4);       // 0
    gaf_kernel<<<NIMG, 128>>>(x_raw);                                  // 1
    conv1_ffma2<<<dim3(NIMG, 4, 8), 128>>>(gaf, wr1, b1, h1);          // 2
    conv_mma<32, 64, 64, 256, 4, 2, true>  <<<NIMG * 1024 / 256, 256, smem2>>>(h1, wr2, b2, h2);  // 3
    conv_mma<64, 32, 128, 128, 2, 4, true> <<<NIMG * 256  / 128, 256, smem3>>>(h2, wr3, b3, h3);  // 4
    conv_mma<128, 16, 256, 64, 2, 4, false><<<NIMG * 64   / 64,  256, smem4>>>(h3, wr4, b4, h4);  // 5
    pool1<<<NIMG, 256>>>();                                            // 6
    pool2<<<BB, 256>>>();                                              // 7
    fc_kernel<<<BB, LATENT>>>(Wfc, bfc, out);                          // 8
}

// round 11
// speedup vs baseline: 1.4451x; 1.1798x over previous
#include <cuda_runtime.h>
#include <cstdint>
#include <math.h>

// Problem constants
#define BB 16
#define CC 32
#define TT 512
#define SS 128       // GAF_SIZE
#define NIMG (BB*CC) // 512
#define LATENT 128

// ---------------- scratch (no allocation allowed) ----------------
__device__ float g_gaf[(size_t)NIMG * 2 * SS * SS];      // NCHW (input to L1)
__device__ float g_h1 [(size_t)NIMG * 64 * 64 * 32];     // NHWC, tf32-rounded
__device__ float g_h2 [(size_t)NIMG * 32 * 32 * 64];     // NHWC, tf32-rounded
__device__ float g_h3 [(size_t)NIMG * 16 * 16 * 128];    // NHWC, tf32-rounded
__device__ float g_h4 [(size_t)NIMG * 8 * 8 * 256];      // NHWC, fp32
__device__ float g_pp  [NIMG * 256];
__device__ float g_pbar[BB * 256];
__device__ float g_wr1[2 * 9 * 32];                      // L1: [ci][t][cout]
__device__ float g_wr2[(32 * 9)  * 64];                  // [k][cout], tf32 bits
__device__ float g_wr3[(64 * 9)  * 128];
__device__ float g_wr4[(128 * 9) * 256];

// ---------------- helpers ----------------
__device__ __forceinline__ uint32_t f2tf32(float f) {
    uint32_t o;
    asm("cvt.rna.tf32.f32 %0, %1;" : "=r"(o) : "f"(f));
    return o;
}
__device__ __forceinline__ float f2tf32f(float f) {
    return __uint_as_float(f2tf32(f));
}
__device__ __forceinline__ void mma_tf32(float* d, const uint32_t* a, const uint32_t* b) {
    asm volatile(
        "mma.sync.aligned.m16n8k8.row.col.f32.tf32.tf32.f32 "
        "{%0,%1,%2,%3}, {%4,%5,%6,%7}, {%8,%9}, {%0,%1,%2,%3};"
        : "+f"(d[0]), "+f"(d[1]), "+f"(d[2]), "+f"(d[3])
        : "r"(a[0]), "r"(a[1]), "r"(a[2]), "r"(a[3]), "r"(b[0]), "r"(b[1]));
}
__device__ __forceinline__ uint32_t smem_u32(const void* p) {
    uint32_t a;
    asm("{ .reg .u64 t; cvta.to.shared.u64 t, %1; cvt.u32.u64 %0, t; }" : "=r"(a) : "l"(p));
    return a;
}
__device__ __forceinline__ void cpasync16(uint32_t dst, const void* src, int srcsize) {
    asm volatile("cp.async.cg.shared.global [%0], [%1], 16, %2;"
                 :: "r"(dst), "l"(src), "r"(srcsize) : "memory");
}
#define CP_COMMIT() asm volatile("cp.async.commit_group;" ::: "memory")
#define CP_WAIT1()  asm volatile("cp.async.wait_group 1;" ::: "memory")
#define CP_WAIT0()  asm volatile("cp.async.wait_group 0;" ::: "memory")

// ---------------- f32x2 helpers (L1 conv) ----------------
__device__ __forceinline__ unsigned long long pk2(float a, float b) {
    unsigned long long r;
    asm("mov.b64 %0, {%1, %2};" : "=l"(r) : "f"(a), "f"(b));
    return r;
}
__device__ __forceinline__ void upk2(unsigned long long v, float& a, float& b) {
    asm("mov.b64 {%0, %1}, %2;" : "=f"(a), "=f"(b) : "l"(v));
}
__device__ __forceinline__ void fma2(unsigned long long& d, unsigned long long a, unsigned long long b) {
    asm("fma.rn.f32x2 %0, %1, %2, %3;" : "=l"(d) : "l"(a), "l"(b), "l"(d));
}

// ---------------- merged weight repack ----------------
__device__ __forceinline__ void rp_tc(const float* __restrict__ W, uint32_t* __restrict__ Br,
                                      int CIN, int COUT, int idx)
{
    int co = idx % COUT;
    int k  = idx / COUT;
    int t  = k / CIN;
    int ci = k % CIN;
    Br[idx] = f2tf32(W[((size_t)co * CIN + ci) * 9 + t]);
}
__global__ void repack_all(const float* __restrict__ W1, const float* __restrict__ W2,
                           const float* __restrict__ W3, const float* __restrict__ W4)
{
    int idx = blockIdx.x * blockDim.x + threadIdx.x;
    if (idx < 576) {                       // L1: W[32][2][3][3] -> [ci][t][cout]
        int co = idx % 32;
        int t  = (idx / 32) % 9;
        int ci = idx / (32 * 9);
        g_wr1[idx] = W1[((size_t)co * 2 + ci) * 9 + t];
        return;
    }
    idx -= 576;
    if (idx < 288 * 64)  { rp_tc(W2, (uint32_t*)g_wr2, 32, 64, idx);  return; }
    idx -= 288 * 64;
    if (idx < 576 * 128) { rp_tc(W3, (uint32_t*)g_wr3, 64, 128, idx); return; }
    idx -= 576 * 128;
    if (idx < 1152 * 256) rp_tc(W4, (uint32_t*)g_wr4, 128, 256, idx);
}

// ---------------- GAF kernel (NCHW out), coalesced row stores ----------------
__global__ void gaf_kernel(const float* __restrict__ x_raw)
{
    const int img = blockIdx.x;
    const int tid = threadIdx.x;   // 0..127
    __shared__ float xs[SS];
    __shared__ float ssq[SS];
    __shared__ float smn[4], smx[4];

    const float4 v4 = *(const float4*)(x_raw + (size_t)img * TT + tid * 4);
    float v = 0.25f * (v4.x + v4.y + v4.z + v4.w);

    float mn = v, mx = v;
    #pragma unroll
    for (int o = 16; o > 0; o >>= 1) {
        mn = fminf(mn, __shfl_xor_sync(0xffffffffu, mn, o));
        mx = fmaxf(mx, __shfl_xor_sync(0xffffffffu, mx, o));
    }
    const int warp = tid >> 5, lane = tid & 31;
    if (lane == 0) { smn[warp] = mn; smx[warp] = mx; }
    __syncthreads();
    mn = fminf(fminf(smn[0], smn[1]), fminf(smn[2], smn[3]));
    mx = fmaxf(fmaxf(smx[0], smx[1]), fmaxf(smx[2], smx[3]));

    float xn = 2.0f * (v - mn) / (mx - mn + 1e-8f) - 1.0f;
    xn = fminf(1.0f, fmaxf(-1.0f, xn));
    float sq = sqrtf(fminf(1.0f, fmaxf(0.0f, 1.0f - xn * xn)));
    xs[tid] = xn;
    ssq[tid] = sq;
    __syncthreads();

    const int c0 = lane * 4;
    float xj[4], sj[4];
    #pragma unroll
    for (int c = 0; c < 4; c++) { xj[c] = xs[c0 + c]; sj[c] = ssq[c0 + c]; }
    float* __restrict__ g0 = g_gaf + (size_t)img * (2 * SS * SS);
    float* __restrict__ g1 = g0 + SS * SS;
    for (int rb = 0; rb < SS; rb += 4) {
        const int row = rb + warp;
        const float xi = xs[row], si = ssq[row];
        float4 o0, o1;
        o0.x = xi * xj[0] - si * sj[0];  o1.x = si * xj[0] - xi * sj[0];
        o0.y = xi * xj[1] - si * sj[1];  o1.y = si * xj[1] - xi * sj[1];
        o0.z = xi * xj[2] - si * sj[2];  o1.z = si * xj[2] - xi * sj[2];
        o0.w = xi * xj[3] - si * sj[3];  o1.w = si * xj[3] - xi * sj[3];
        *(float4*)(g0 + row * SS + c0) = o0;
        *(float4*)(g1 + row * SS + c0) = o1;
    }
}

// ---------------- L1 direct conv (FFMA2), NCHW in -> NHWC out (tf32-rounded) --------
__global__ void __launch_bounds__(128)
conv1_ffma2(const float* __restrict__ in, const float* __restrict__ Wr,
            const float* __restrict__ bias, float* __restrict__ out)
{
    constexpr int CIN = 2, HIN = 128, COUT = 32, HOUT = 64, WQ = 16;
    const int tid  = threadIdx.x;
    const int sid  = tid + blockIdx.z * 128;
    const int n    = blockIdx.x;
    const int cout0 = blockIdx.y * 8;
    const int oh  = sid / WQ;
    const int ow0 = (sid % WQ) * 4;

    const float* __restrict__ inN = in + (size_t)n * CIN * HIN * HIN;

    unsigned long long acc[4][4];
    #pragma unroll
    for (int cp = 0; cp < 4; cp++)
        #pragma unroll
        for (int o = 0; o < 4; o++) acc[cp][o] = 0ull;

    const bool rguard = (ow0 * 2 + 8 < HIN);

    #pragma unroll
    for (int ci = 0; ci < CIN; ci++) {
        const float* __restrict__ wbase = Wr + ((size_t)ci * 9) * COUT + cout0;
        const float* __restrict__ inC = inN + (size_t)ci * HIN * HIN;
        #pragma unroll
        for (int kh = 0; kh < 3; kh++) {
            const int ih = oh * 2 + kh;
            if (ih >= HIN) break;
            const float* row = inC + (size_t)ih * HIN + ow0 * 2;
            float r[9];
            const float4 a = *(const float4*)row;
            const float4 b = *(const float4*)(row + 4);
            r[0]=a.x; r[1]=a.y; r[2]=a.z; r[3]=a.w;
            r[4]=b.x; r[5]=b.y; r[6]=b.z; r[7]=b.w;
            r[8] = rguard ? row[8] : 0.0f;
            unsigned long long pb[9];
            #pragma unroll
            for (int v = 0; v < 9; v++) pb[v] = pk2(r[v], r[v]);
            #pragma unroll
            for (int kw = 0; kw < 3; kw++) {
                const float* wp = wbase + (kh * 3 + kw) * COUT;
                const ulonglong2 wa = *(const ulonglong2*)(wp);
                const ulonglong2 wb = *(const ulonglong2*)(wp + 4);
                #pragma unroll
                for (int o = 0; o < 4; o++) {
                    const unsigned long long x = pb[2 * o + kw];
                    fma2(acc[0][o], wa.x, x);
                    fma2(acc[1][o], wa.y, x);
                    fma2(acc[2][o], wb.x, x);
                    fma2(acc[3][o], wb.y, x);
                }
            }
        }
    }

    float bv[8];
    #pragma unroll
    for (int c = 0; c < 8; c++) bv[c] = __ldg(bias + cout0 + c);
    #pragma unroll
    for (int o = 0; o < 4; o++) {
        float l0,h0,l1,h1,l2,h2,l3,h3;
        upk2(acc[0][o], l0, h0); upk2(acc[1][o], l1, h1);
        upk2(acc[2][o], l2, h2); upk2(acc[3][o], l3, h3);
        float4 vlo, vhi;   // tf32-round outputs so downstream MMA truncation is exact
        vlo.x = f2tf32f(fmaxf(l0 + bv[0], 0.f)); vlo.y = f2tf32f(fmaxf(h0 + bv[1], 0.f));
        vlo.z = f2tf32f(fmaxf(l1 + bv[2], 0.f)); vlo.w = f2tf32f(fmaxf(h1 + bv[3], 0.f));
        vhi.x = f2tf32f(fmaxf(l2 + bv[4], 0.f)); vhi.y = f2tf32f(fmaxf(h2 + bv[5], 0.f));
        vhi.z = f2tf32f(fmaxf(l3 + bv[6], 0.f)); vhi.w = f2tf32f(fmaxf(h3 + bv[7], 0.f));
        float* op = out + (((size_t)n * HOUT + oh) * HOUT + (ow0 + o)) * COUT + cout0;
        *(float4*)op = vlo;
        *(float4*)(op + 4) = vhi;
    }
}

// ---------------- tf32 mma.sync implicit-GEMM conv ----------------
// 128-thread CTAs (4 warps), 3-stage cp.async ring, 1 sync/chunk, 2 CTAs/SM.
// in: NHWC (tf32-rounded); Br: [k][COUTG] tf32 bits; out: NHWC (COUTG stride).
// N tile = NTILE (blockIdx.y selects which NTILE-wide slice of COUTG).
template<int CIN, int HIN, int COUTG, int NTILE, int TM, int WM, int WN, bool CVTOUT>
__global__ void __launch_bounds__(128)
conv_mma(const float* __restrict__ in, const float* __restrict__ Br,
         const float* __restrict__ bias, float* __restrict__ out)
{
    static_assert(WM * WN == 4, "4 warps");
    constexpr int HOUT = HIN / 2;
    constexpr int P    = HOUT * HOUT;
    constexpr int K    = CIN * 9;
    constexpr int NCH  = K / 32;
    constexpr int CPT  = CIN / 32;
    constexpr int MF   = TM / (WM * 16);   // m fragments per warp
    constexpr int WNT  = NTILE / WN;       // warp n-tile
    constexpr int NF   = WNT / 8;          // n fragments per warp
    constexpr int AST  = 36;               // A smem row stride (floats)
    constexpr int BST  = NTILE + 8;        // B smem row stride (floats)
    constexpr int AFL  = TM * AST;
    constexpr int BFL  = 32 * BST;
    constexpr int SFL  = AFL + BFL;        // floats per stage
    constexpr int TPR  = 128 / TM;         // threads per A row
    constexpr int CHK  = 8 / TPR;          // 16B chunks per thread (A row = 128B)
    constexpr int BCH  = NTILE / 16;       // B cp.async iterations per thread

    extern __shared__ float smf[];
    const uint32_t sm0 = smem_u32(smf);

    const int tid  = threadIdx.x;
    const int lane = tid & 31;
    const int wid  = tid >> 5;
    const int wm   = wid % WM;
    const int wn   = wid / WM;
    const int g    = lane >> 2;           // 0..7
    const int tq   = lane & 3;            // 0..3

    // A staging coords
    const int r    = tid / TPR;
    const int sub  = tid % TPR;
    const int pos  = blockIdx.x * TM + r;
    const int nimg = pos / P;
    const int rem  = pos % P;
    const int oh   = rem / HOUT, ow = rem % HOUT;
    const int ncta = blockIdx.y * NTILE;

    const uint32_t a_dst_off = (uint32_t)(r * AST + sub * CHK * 4) * 4;

    auto prefetch = [&](int kc, int slot) {
        const uint32_t sbase = sm0 + (uint32_t)(slot * SFL) * 4;
        const int t   = kc / CPT;
        const int ci0 = (kc % CPT) * 32;
        const int kh = t / 3, kw = t % 3;
        const int ih = oh * 2 + kh, iw = ow * 2 + kw;
        const bool val = (ih < HIN) && (iw < HIN);
        const float* s = val
            ? in + ((((size_t)nimg * HIN + ih) * HIN + iw) * CIN + ci0) + sub * CHK * 4
            : in;
        const int sz = val ? 16 : 0;
        const uint32_t ad = sbase + a_dst_off;
        #pragma unroll
        for (int c = 0; c < CHK; c++)
            cpasync16(ad + c * 16, s + c * 4, sz);
        // B: 32 rows x NTILE floats (from COUTG-stride source)
        const uint32_t bd = sbase + (uint32_t)AFL * 4;
        #pragma unroll
        for (int j = 0; j < BCH; j++) {
            const int cid = j * 128 + tid;
            const int k   = cid / (NTILE / 4);
            const int cc  = cid % (NTILE / 4);
            cpasync16(bd + (uint32_t)(k * BST + cc * 4) * 4,
                      Br + (size_t)(kc * 32 + k) * COUTG + ncta + cc * 4, 16);
        }
    };

    prefetch(0, 0); CP_COMMIT();
    prefetch(1, 1); CP_COMMIT();

    float d[MF][NF][4];
    #pragma unroll
    for (int mf = 0; mf < MF; mf++)
        #pragma unroll
        for (int nf = 0; nf < NF; nf++)
            #pragma unroll
            for (int j = 0; j < 4; j++) d[mf][nf][j] = 0.f;

    int slot = 0;
    for (int c = 0; c < NCH; c++) {
        if (c + 1 < NCH) { CP_WAIT1(); } else { CP_WAIT0(); }
        __syncthreads();
        if (c + 2 < NCH) {
            int ps = slot + 2; if (ps >= 3) ps -= 3;
            prefetch(c + 2, ps);
            CP_COMMIT();
        }

        const uint32_t* A = (const uint32_t*)(smf + slot * SFL);
        const uint32_t* B = A + AFL;
        #pragma unroll
        for (int ks = 0; ks < 4; ks++) {
            uint32_t a[MF][4], b[NF][2];
            const int ac = ks * 8 + tq;
            #pragma unroll
            for (int mf = 0; mf < MF; mf++) {
                const int ar = wm * (16 * MF) + mf * 16 + g;
                a[mf][0] = A[ar * AST + ac];
                a[mf][1] = A[(ar + 8) * AST + ac];
                a[mf][2] = A[ar * AST + ac + 4];
                a[mf][3] = A[(ar + 8) * AST + ac + 4];
            }
            const int bkr = ks * 8 + tq;
            #pragma unroll
            for (int nf = 0; nf < NF; nf++) {
                const int bcc = wn * WNT + nf * 8 + g;
                b[nf][0] = B[bkr * BST + bcc];
                b[nf][1] = B[(bkr + 4) * BST + bcc];
            }
            #pragma unroll
            for (int mf = 0; mf < MF; mf++)
                #pragma unroll
                for (int nf = 0; nf < NF; nf++)
                    mma_tf32(d[mf][nf], a[mf], b[nf]);
        }
        if (++slot == 3) slot = 0;
    }

    // epilogue: bias + ReLU (+ optional tf32 round), NHWC float2 stores
    #pragma unroll
    for (int nf = 0; nf < NF; nf++) {
        const int col = ncta + wn * WNT + nf * 8 + 2 * tq;
        const float b0 = __ldg(bias + col);
        const float b1 = __ldg(bias + col + 1);
        #pragma unroll
        for (int mf = 0; mf < MF; mf++) {
            const int row0 = blockIdx.x * TM + wm * (16 * MF) + mf * 16 + g;
            float2 v0, v1;
            v0.x = fmaxf(d[mf][nf][0] + b0, 0.f);
            v0.y = fmaxf(d[mf][nf][1] + b1, 0.f);
            v1.x = fmaxf(d[mf][nf][2] + b0, 0.f);
            v1.y = fmaxf(d[mf][nf][3] + b1, 0.f);
            if (CVTOUT) {
                v0.x = f2tf32f(v0.x); v0.y = f2tf32f(v0.y);
                v1.x = f2tf32f(v1.x); v1.y = f2tf32f(v1.y);
            }
            *(float2*)(out + (size_t)row0 * COUTG + col)       = v0;
            *(float2*)(out + (size_t)(row0 + 8) * COUTG + col) = v1;
        }
    }
}

// ---------------- pool stage 1: per image, sum 64 positions ----------------
__global__ void pool1()
{
    const int img = blockIdx.x;
    const int k = threadIdx.x;  // 0..255
    const float* __restrict__ base = g_h4 + (size_t)img * 64 * 256 + k;
    float s = 0.0f;
    #pragma unroll
    for (int i = 0; i < 64; i++)
        s += base[(size_t)i * 256];
    g_pp[img * 256 + k] = s;
}
// ---------------- pool stage 2: sum over C=32 heads ----------------
__global__ void pool2()
{
    const int b = blockIdx.x;
    const int k = threadIdx.x;
    const float* __restrict__ p = g_pp + (size_t)b * 32 * 256 + k;
    float s = 0.0f;
    #pragma unroll
    for (int c = 0; c < 32; c++)
        s += p[(size_t)c * 256];
    g_pbar[b * 256 + k] = s * (1.0f / 2048.0f);
}

// ---------------- FC ----------------
__global__ void fc_kernel(const float* __restrict__ Wfc, const float* __restrict__ bfc,
                          float* __restrict__ out)
{
    const int b = blockIdx.x;
    const int l = threadIdx.x;
    float s = bfc[l];
    const float* p = g_pbar + b * 256;
    #pragma unroll 8
    for (int k = 0; k < 256; k++)
        s = fmaf(p[k], Wfc[k * LATENT + l], s);
    out[b * LATENT + l] = s;
}

// ---------------- launch ----------------
extern "C" void kernel_launch(void* const* d_in, const int* in_sizes, int n_in,
                              void* d_out, int out_size)
{
    const float* x_raw = (const float*)d_in[0];
    const float* W1 = (const float*)d_in[1];  const float* b1 = (const float*)d_in[2];
    const float* W2 = (const float*)d_in[3];  const float* b2 = (const float*)d_in[4];
    const float* W3 = (const float*)d_in[5];  const float* b3 = (const float*)d_in[6];
    const float* W4 = (const float*)d_in[7];  const float* b4 = (const float*)d_in[8];
    const float* Wfc = (const float*)d_in[9]; const float* bfc = (const float*)d_in[10];
    float* out = (float*)d_out;

    float *gaf, *h1, *h2, *h3, *h4, *wr1, *wr2, *wr3, *wr4;
    cudaGetSymbolAddress((void**)&gaf, g_gaf);
    cudaGetSymbolAddress((void**)&h1, g_h1);
    cudaGetSymbolAddress((void**)&h2, g_h2);
    cudaGetSymbolAddress((void**)&h3, g_h3);
    cudaGetSymbolAddress((void**)&h4, g_h4);
    cudaGetSymbolAddress((void**)&wr1, g_wr1);
    cudaGetSymbolAddress((void**)&wr2, g_wr2);
    cudaGetSymbolAddress((void**)&wr3, g_wr3);
    cudaGetSymbolAddress((void**)&wr4, g_wr4);

    // 3 stages of (A + B) floats; ~80KB per CTA -> 2 CTAs/SM
    const int smem2 = 3 * (128 * 36 + 32 * 72)  * 4;   // 82944
    const int smem3 = 3 * (64  * 36 + 32 * 136) * 4;   // 79872
    const int smem4 = 3 * (64  * 36 + 32 * 136) * 4;   // 79872
    cudaFuncSetAttribute((const void*)conv_mma<32, 64, 64, 64, 128, 2, 2, true>,
                         cudaFuncAttributeMaxDynamicSharedMemorySize, smem2);
    cudaFuncSetAttribute((const void*)conv_mma<64, 32, 128, 128, 64, 2, 2, true>,
                         cudaFuncAttributeMaxDynamicSharedMemorySize, smem3);
    cudaFuncSetAttribute((const void*)conv_mma<128, 16, 256, 128, 64, 2, 2, false>,
                         cudaFuncAttributeMaxDynamicSharedMemorySize, smem4);

    const int rp_total = 576 + 288 * 64 + 576 * 128 + 1152 * 256;

    repack_all<<<(rp_total + 255) / 256, 256>>>(W1, W2, W3, W4);       // 0
    gaf_kernel<<<NIMG, 128>>>(x_raw);                                  // 1
    conv1_ffma2<<<dim3(NIMG, 4, 8), 128>>>(gaf, wr1, b1, h1);          // 2
    // L2: 2->... TM=128, warp tile 64x32 (MF=4, NF=4)
    conv_mma<32, 64, 64, 64, 128, 2, 2, true>
        <<<dim3(NIMG * 1024 / 128, 1), 128, smem2>>>(h1, wr2, b2, h2); // 3
    // L3: TM=64, warp tile 32x64 (MF=2, NF=8)
    conv_mma<64, 32, 128, 128, 64, 2, 2, true>
        <<<dim3(NIMG * 256 / 64, 1), 128, smem3>>>(h2, wr3, b3, h3);   // 4
    // L4: TM=64, N split 2x128, warp tile 32x64 (MF=2, NF=8)
    conv_mma<128, 16, 256, 128, 64, 2, 2, false>
        <<<dim3(NIMG * 64 / 64, 2), 128, smem4>>>(h3, wr4, b4, h4);    // 5
    pool1<<<NIMG, 256>>>();                                            // 6
    pool2<<<BB, 256>>>();                                              // 7
    fc_kernel<<<BB, LATENT>>>(Wfc, bfc, out);                          // 8
}